// round 1
// baseline (speedup 1.0000x reference)
#include <cuda_runtime.h>
#include <math.h>

// ---- problem constants ----
#define BB   8
#define CC   384
#define HH   32
#define WW   32
#define LL   1024      // HH*WW
#define NHH  8
#define DKK  48
#define DVV  48
#define CFF_ 1536
#define NBIAS_ 3969
#define LN_EPS_ 1e-5f

// ---- scratch (device globals; no runtime allocation allowed) ----
__device__ float g_tok [BB*LL*CC];        // LN output, [b*L+l][c]
__device__ float g_q   [BB*NHH*LL*DKK];   // [((b*NH+h)*L+l)*DK+d]
__device__ float g_k   [BB*NHH*LL*DKK];
__device__ float g_v   [BB*NHH*LL*DKK];
__device__ float g_attn[BB*LL*NHH*DVV];   // [(b*L+l)*384 + h*48+d]
__device__ float g_ytok[BB*LL*CC];        // y (token-major), [b*L+l][c]
__device__ float g_u1  [BB*LL*CFF_];      // gelu(fc1) activations

// ============================================================
// LayerNorm over channels per spatial token.
// grid = B*L, block = 128 (3 channels per thread)
// ============================================================
__global__ void ln_kernel(const float* __restrict__ x,
                          const float* __restrict__ gamma,
                          const float* __restrict__ beta,
                          float* __restrict__ tok)
{
    int bl = blockIdx.x;
    int b  = bl >> 10;
    int l  = bl & 1023;
    int tid = threadIdx.x;

    float v0 = x[(b*CC + tid      )*LL + l];
    float v1 = x[(b*CC + tid + 128)*LL + l];
    float v2 = x[(b*CC + tid + 256)*LL + l];

    __shared__ float red[128];
    red[tid] = v0 + v1 + v2;
    __syncthreads();
    for (int o = 64; o > 0; o >>= 1) {
        if (tid < o) red[tid] += red[tid + o];
        __syncthreads();
    }
    float mu = red[0] * (1.0f / 384.0f);
    __syncthreads();

    float d0 = v0 - mu, d1 = v1 - mu, d2 = v2 - mu;
    red[tid] = d0*d0 + d1*d1 + d2*d2;
    __syncthreads();
    for (int o = 64; o > 0; o >>= 1) {
        if (tid < o) red[tid] += red[tid + o];
        __syncthreads();
    }
    float inv = rsqrtf(red[0] * (1.0f / 384.0f) + LN_EPS_);

    float* t = &tok[(b*LL + l)*CC];
    t[tid      ] = d0 * inv * gamma[tid      ] + beta[tid      ];
    t[tid + 128] = d1 * inv * gamma[tid + 128] + beta[tid + 128];
    t[tid + 256] = d2 * inv * gamma[tid + 256] + beta[tid + 256];
}

// ============================================================
// Generic tiled fp32 GEMM:  Out = A[M,K] * W[N,K]^T (+bias) with epilogues
// 64x64 tile, 16x16 threads, 4x4 per thread, BK=16.
// MODE 0: plain     Out[row*N+col] = v
// MODE 1: GELU      Out[row*N+col] = gelu(v)
// MODE 2: head-scatter (QKV):  Out[((b*8+h)*1024+l)*48+d] = v
// MODE 3: +x residual (transposed read): Out[row*384+col] = v + aux[(b*384+col)*1024+l]
// MODE 4: transposed store + residual:   Out[(b*384+col)*1024+l] = v + aux[row*384+col]
// ============================================================
template<int MODE>
__global__ void gemm64(const float* __restrict__ A,
                       const float* __restrict__ W,
                       const float* __restrict__ bias,
                       float* __restrict__ Out,
                       int M, int N, int K,
                       const float* __restrict__ aux)
{
    __shared__ float As[16][64];
    __shared__ float Bs[16][64];

    int tx = threadIdx.x, ty = threadIdx.y;
    int tid = ty * 16 + tx;
    int m0 = blockIdx.y * 64;
    int n0 = blockIdx.x * 64;

    float acc[4][4];
    #pragma unroll
    for (int i = 0; i < 4; i++)
        #pragma unroll
        for (int j = 0; j < 4; j++) acc[i][j] = 0.f;

    for (int k0 = 0; k0 < K; k0 += 16) {
        #pragma unroll
        for (int i = 0; i < 4; i++) {
            int e = tid + i * 256;
            int r = e >> 4, c = e & 15;
            As[c][r] = A[(size_t)(m0 + r) * K + k0 + c];
            Bs[c][r] = W[(size_t)(n0 + r) * K + k0 + c];
        }
        __syncthreads();
        #pragma unroll
        for (int kk = 0; kk < 16; kk++) {
            float a[4], bb[4];
            #pragma unroll
            for (int i = 0; i < 4; i++) a[i]  = As[kk][ty*4 + i];
            #pragma unroll
            for (int j = 0; j < 4; j++) bb[j] = Bs[kk][tx*4 + j];
            #pragma unroll
            for (int i = 0; i < 4; i++)
                #pragma unroll
                for (int j = 0; j < 4; j++)
                    acc[i][j] += a[i] * bb[j];
        }
        __syncthreads();
    }

    #pragma unroll
    for (int i = 0; i < 4; i++) {
        #pragma unroll
        for (int j = 0; j < 4; j++) {
            int row = m0 + ty*4 + i;
            int col = n0 + tx*4 + j;
            float v = acc[i][j] + (bias ? bias[col] : 0.f);
            if (MODE == 0) {
                Out[(size_t)row * N + col] = v;
            } else if (MODE == 1) {
                Out[(size_t)row * N + col] =
                    0.5f * v * (1.0f + erff(v * 0.70710678118654752f));
            } else if (MODE == 2) {
                int b = row >> 10, l = row & 1023;
                int h = col / 48,  d = col % 48;
                Out[(size_t)(((b*8 + h) * 1024) + l) * 48 + d] = v;
            } else if (MODE == 3) {
                int b = row >> 10, l = row & 1023;
                Out[(size_t)row * 384 + col] =
                    v + aux[(size_t)(b*384 + col) * 1024 + l];
            } else { // MODE == 4
                int b = row >> 10, l = row & 1023;
                Out[(size_t)(b*384 + col) * 1024 + l] =
                    v + aux[(size_t)row * 384 + col];
            }
        }
    }
}

// ============================================================
// Flash-style attention with relative position bias.
// grid = (L/16, B*NH), block = 128.
// Each block: 16 query rows for one (b,h); streams K/V in 64-key chunks.
// Bias index computed analytically: idx=(my-ly+32)*32+(mx-lx+32).
// ============================================================
#define QT 16
#define MC 64
__global__ void attn_kernel(const float* __restrict__ q,
                            const float* __restrict__ k,
                            const float* __restrict__ v,
                            const float* __restrict__ rel_bias,
                            float* __restrict__ attn_out)
{
    int b  = blockIdx.y >> 3;
    int h  = blockIdx.y & 7;
    int q0 = blockIdx.x * QT;
    int tid = threadIdx.x;

    __shared__ float sq[QT][DKK];
    __shared__ float sK[MC][DKK];
    __shared__ float sV[MC][DKK];
    __shared__ float sS[QT][MC];
    __shared__ float sO[QT][DKK];
    __shared__ float sM[QT], sSum[QT], sAl[QT];

    const float* qbase = &q[(size_t)((b*NHH + h) * LL) * DKK];
    const float* kbase = &k[(size_t)((b*NHH + h) * LL) * DKK];
    const float* vbase = &v[(size_t)((b*NHH + h) * LL) * DKK];
    const float* biasrow = &rel_bias[(size_t)h * NBIAS_];

    for (int e = tid; e < QT*DKK; e += 128) {
        sq[e / DKK][e % DKK] = qbase[(size_t)(q0 + e / DKK) * DKK + (e % DKK)];
        sO[e / DKK][e % DKK] = 0.f;
    }
    if (tid < QT) { sM[tid] = -1e30f; sSum[tid] = 0.f; }
    __syncthreads();

    for (int m0 = 0; m0 < LL; m0 += MC) {
        // stage K/V chunk
        for (int e = tid; e < MC*DKK; e += 128) {
            int r = e / DKK, c = e % DKK;
            sK[r][c] = kbase[(size_t)(m0 + r) * DKK + c];
            sV[r][c] = vbase[(size_t)(m0 + r) * DKK + c];
        }
        __syncthreads();

        // scores + bias
        for (int slot = tid; slot < QT*MC; slot += 128) {
            int r = slot / MC, mm = slot % MC;
            const float* qr = sq[r];
            const float* kr = sK[mm];
            float acc = 0.f;
            #pragma unroll
            for (int d2 = 0; d2 < DKK; d2++) acc += qr[d2] * kr[d2];
            int l = q0 + r, m = m0 + mm;
            int idx = ((m >> 5) - (l >> 5) + 32) * 32 + ((m & 31) - (l & 31) + 32);
            sS[r][mm] = acc + biasrow[idx];
        }
        __syncthreads();

        // online softmax: 8 threads per row
        {
            int r = tid >> 3, u = tid & 7;
            float cmax = -1e30f;
            for (int mm = u; mm < MC; mm += 8) cmax = fmaxf(cmax, sS[r][mm]);
            #pragma unroll
            for (int o = 4; o > 0; o >>= 1)
                cmax = fmaxf(cmax, __shfl_xor_sync(0xffffffffu, cmax, o));
            float newM = fmaxf(sM[r], cmax);
            float al = expf(sM[r] - newM);
            float ssum = 0.f;
            for (int mm = u; mm < MC; mm += 8) {
                float p = expf(sS[r][mm] - newM);
                sS[r][mm] = p;
                ssum += p;
            }
            #pragma unroll
            for (int o = 4; o > 0; o >>= 1)
                ssum += __shfl_xor_sync(0xffffffffu, ssum, o);
            if (u == 0) {
                sSum[r] = sSum[r] * al + ssum;
                sM[r]   = newM;
                sAl[r]  = al;
            }
        }
        __syncthreads();

        // accumulate P*V
        for (int slot = tid; slot < QT*DKK; slot += 128) {
            int r = slot / DKK, d = slot % DKK;
            float acc = 0.f;
            #pragma unroll 8
            for (int mm = 0; mm < MC; mm++) acc += sS[r][mm] * sV[mm][d];
            sO[r][d] = sO[r][d] * sAl[r] + acc;
        }
        __syncthreads();
    }

    // normalize + write [b, l, h*48+d]
    for (int slot = tid; slot < QT*DKK; slot += 128) {
        int r = slot / DKK, d = slot % DKK;
        attn_out[(size_t)(b*LL + q0 + r) * (NHH*DVV) + h*DVV + d] =
            sO[r][d] / sSum[r];
    }
}

// ============================================================
// launch
// ============================================================
extern "C" void kernel_launch(void* const* d_in, const int* in_sizes, int n_in,
                              void* d_out, int out_size)
{
    (void)in_sizes; (void)n_in; (void)out_size;
    const float* x        = (const float*)d_in[0];
    const float* gamma    = (const float*)d_in[1];
    const float* beta     = (const float*)d_in[2];
    const float* Wq       = (const float*)d_in[3];
    const float* Wk       = (const float*)d_in[4];
    const float* Wv       = (const float*)d_in[5];
    const float* Wo       = (const float*)d_in[6];
    const float* bo       = (const float*)d_in[7];
    const float* rel_bias = (const float*)d_in[8];
    const float* fc1_w    = (const float*)d_in[9];
    const float* fc1_b    = (const float*)d_in[10];
    const float* fc2_w    = (const float*)d_in[11];
    const float* fc2_b    = (const float*)d_in[12];
    // d_in[13] (rel_idx) unused: bias index computed analytically in-kernel.
    float* out = (float*)d_out;

    float *tok, *q, *k, *v, *attn, *ytok, *u1;
    cudaGetSymbolAddress((void**)&tok,  g_tok);
    cudaGetSymbolAddress((void**)&q,    g_q);
    cudaGetSymbolAddress((void**)&k,    g_k);
    cudaGetSymbolAddress((void**)&v,    g_v);
    cudaGetSymbolAddress((void**)&attn, g_attn);
    cudaGetSymbolAddress((void**)&ytok, g_ytok);
    cudaGetSymbolAddress((void**)&u1,   g_u1);

    const int M = BB * LL;        // 8192
    dim3 tb(16, 16);

    // 1) LayerNorm
    ln_kernel<<<M, 128>>>(x, gamma, beta, tok);

    // 2) Q/K/V projections (head-scatter epilogue)
    gemm64<2><<<dim3(384/64, M/64), tb>>>(tok, Wq, nullptr, q,  M, 384, 384, nullptr);
    gemm64<2><<<dim3(384/64, M/64), tb>>>(tok, Wk, nullptr, k,  M, 384, 384, nullptr);
    gemm64<2><<<dim3(384/64, M/64), tb>>>(tok, Wv, nullptr, v,  M, 384, 384, nullptr);

    // 3) attention with relative bias
    attn_kernel<<<dim3(LL/QT, BB*NHH), 128>>>(q, k, v, rel_bias, attn);

    // 4) output projection + residual with x  ->  y (token-major)
    gemm64<3><<<dim3(384/64, M/64), tb>>>(attn, Wo, bo, ytok, M, 384, 384, x);

    // 5) fc1 + exact GELU
    gemm64<1><<<dim3(1536/64, M/64), tb>>>(ytok, fc1_w, fc1_b, u1, M, 1536, 384, nullptr);

    // 6) fc2 + residual with y, store transposed to (B,C,H,W)
    gemm64<4><<<dim3(384/64, M/64), tb>>>(u1, fc2_w, fc2_b, out, M, 384, 1536, ytok);
}

// round 2
// speedup vs baseline: 1.5496x; 1.5496x over previous
#include <cuda_runtime.h>
#include <math.h>

// ---- problem constants ----
#define BB   8
#define CC   384
#define LL   1024
#define NHH  8
#define DKK  48
#define DVV  48
#define CFF_ 1536
#define NBIAS_ 3969
#define LN_EPS_ 1e-5f

// ---- scratch ----
__device__ float g_tok [BB*LL*CC];
__device__ float g_q   [BB*NHH*LL*DKK];
__device__ float g_k   [BB*NHH*LL*DKK];
__device__ float g_v   [BB*NHH*LL*DKK];
__device__ float g_attn[BB*LL*NHH*DVV];
__device__ float g_ytok[BB*LL*CC];
__device__ float g_u1  [BB*LL*CFF_];

// ============================================================
// LayerNorm: grid (L/32, B), block (32,8).
// Pass 1: coalesced stats (lane = token, y = channel stride).
// Pass 2: 64-channel chunks staged through smem, coalesced both sides.
// ============================================================
__global__ void ln_kernel(const float* __restrict__ x,
                          const float* __restrict__ gamma,
                          const float* __restrict__ beta,
                          float* __restrict__ tok)
{
    int b  = blockIdx.y;
    int l0 = blockIdx.x * 32;
    int lane = threadIdx.x;      // token within group of 32
    int cy   = threadIdx.y;      // 0..7

    __shared__ float redS [8][32];
    __shared__ float redS2[8][32];
    __shared__ float s_mu[32], s_inv[32];
    __shared__ float buf[64][33];

    float s = 0.f, s2 = 0.f;
    for (int c = cy; c < CC; c += 8) {
        float v = x[((size_t)b*CC + c)*LL + l0 + lane];
        s += v; s2 += v*v;
    }
    redS[cy][lane] = s; redS2[cy][lane] = s2;
    __syncthreads();
    if (cy == 0) {
        float ts = 0.f, ts2 = 0.f;
        #pragma unroll
        for (int i = 0; i < 8; i++) { ts += redS[i][lane]; ts2 += redS2[i][lane]; }
        float mu = ts * (1.0f/384.0f);
        float var = ts2 * (1.0f/384.0f) - mu*mu;
        s_mu[lane] = mu;
        s_inv[lane] = rsqrtf(var + LN_EPS_);
    }
    __syncthreads();

    int tid = cy*32 + lane;
    for (int c0 = 0; c0 < CC; c0 += 64) {
        // load 64 channels x 32 tokens, coalesced along tokens
        for (int e = tid; e < 64*32; e += 256) {
            int c = e >> 5, t = e & 31;
            buf[c][t] = x[((size_t)b*CC + c0 + c)*LL + l0 + t];
        }
        __syncthreads();
        // write token-major, coalesced along channels
        for (int e = tid; e < 64*32; e += 256) {
            int c = e & 63, t = e >> 6;
            float v = (buf[c][t] - s_mu[t]) * s_inv[t];
            tok[((size_t)b*LL + l0 + t)*CC + c0 + c] =
                v * gamma[c0 + c] + beta[c0 + c];
        }
        __syncthreads();
    }
}

// ============================================================
// GEMM: Out = A[M,K] * W[N,K]^T (+bias), 128x64 tile, 256 thr,
// 8x4 per thread, BK=16, float4 LDS, register-staged prefetch.
// MODE 1: GELU   MODE 2: QKV head-scatter
// MODE 3: +x residual (transposed read)  MODE 4: transposed store + residual
// ============================================================
template<int MODE>
__global__ __launch_bounds__(256)
void gemm128(const float* __restrict__ A,
             const float* __restrict__ W,
             const float* __restrict__ bias,
             float* __restrict__ Out,
             int M, int N, int K,
             const float* __restrict__ aux)
{
    __shared__ __align__(16) float As[16][132];
    __shared__ __align__(16) float Bs[16][68];

    const int tid = threadIdx.x;
    const int m0 = blockIdx.y * 128;
    const int n0 = blockIdx.x * 64;
    const int tx = tid & 15;         // n sub-tile
    const int ty = tid >> 4;         // m sub-tile (0..15)

    // staging mapping
    const int ra = tid >> 1, ka = (tid & 1) * 8;   // A: row, k-offset (2 float4)
    const int nb = tid >> 2, kb = (tid & 3) * 4;   // W: row, k-offset (1 float4)

    const float* Ap = A + (size_t)(m0 + ra) * K + ka;
    const float* Wp = W + (size_t)(n0 + nb) * K + kb;

    float4 a0 = *(const float4*)Ap;
    float4 a1 = *(const float4*)(Ap + 4);
    float4 b0 = *(const float4*)Wp;

    float acc[8][4];
    #pragma unroll
    for (int i = 0; i < 8; i++)
        #pragma unroll
        for (int j = 0; j < 4; j++) acc[i][j] = 0.f;

    for (int k0 = 0; k0 < K; k0 += 16) {
        As[ka+0][ra] = a0.x; As[ka+1][ra] = a0.y;
        As[ka+2][ra] = a0.z; As[ka+3][ra] = a0.w;
        As[ka+4][ra] = a1.x; As[ka+5][ra] = a1.y;
        As[ka+6][ra] = a1.z; As[ka+7][ra] = a1.w;
        Bs[kb+0][nb] = b0.x; Bs[kb+1][nb] = b0.y;
        Bs[kb+2][nb] = b0.z; Bs[kb+3][nb] = b0.w;
        __syncthreads();

        if (k0 + 16 < K) {
            Ap += 16; Wp += 16;
            a0 = *(const float4*)Ap;
            a1 = *(const float4*)(Ap + 4);
            b0 = *(const float4*)Wp;
        }

        #pragma unroll
        for (int kk = 0; kk < 16; kk++) {
            float4 av0 = *(const float4*)&As[kk][ty*8];
            float4 av1 = *(const float4*)&As[kk][ty*8 + 4];
            float4 bv  = *(const float4*)&Bs[kk][tx*4];
            float av[8] = {av0.x, av0.y, av0.z, av0.w, av1.x, av1.y, av1.z, av1.w};
            float bb[4] = {bv.x, bv.y, bv.z, bv.w};
            #pragma unroll
            for (int i = 0; i < 8; i++)
                #pragma unroll
                for (int j = 0; j < 4; j++)
                    acc[i][j] += av[i] * bb[j];
        }
        __syncthreads();
    }

    #pragma unroll
    for (int i = 0; i < 8; i++) {
        int row = m0 + ty*8 + i;
        int b = row >> 10, l = row & 1023;
        #pragma unroll
        for (int j = 0; j < 4; j++) {
            int col = n0 + tx*4 + j;
            float v = acc[i][j] + (bias ? bias[col] : 0.f);
            if (MODE == 1) {
                Out[(size_t)row * N + col] =
                    0.5f * v * (1.0f + erff(v * 0.70710678118654752f));
            } else if (MODE == 2) {
                int h = col / 48, d = col % 48;
                Out[(size_t)(((b*8 + h) * 1024) + l) * 48 + d] = v;
            } else if (MODE == 3) {
                Out[(size_t)row * 384 + col] =
                    v + aux[(size_t)(b*384 + col) * 1024 + l];
            } else { // MODE 4
                Out[(size_t)(b*384 + col) * 1024 + l] =
                    v + aux[(size_t)row * 384 + col];
            }
        }
    }
}

// ============================================================
// Flash attention with relative bias.
// grid = (L/64, B*NH), block = 256. QT=64 queries, MC=64 keys/chunk.
// Scores: 4x4 register tile; PV: 4x3 register tile vs transposed V.
// K and V^T share one smem buffer (phased).
// ============================================================
#define QT 64
#define MC 64
#define SK(m,d)  sKV[(m)*48 + (d)]
#define SVT(d,m) sKV[(d)*68 + (m)]

__global__ __launch_bounds__(256)
void attn_kernel(const float* __restrict__ q,
                 const float* __restrict__ k,
                 const float* __restrict__ v,
                 const float* __restrict__ rel_bias,
                 float* __restrict__ attn_out)
{
    int b  = blockIdx.y >> 3;
    int h  = blockIdx.y & 7;
    int q0 = blockIdx.x * QT;
    int tid = threadIdx.x;
    int tx = tid & 15;          // 0..15
    int ty = tid >> 4;          // 0..15

    __shared__ __align__(16) float sq[QT][48];
    __shared__ __align__(16) float sKV[48*68];   // K as [64][48] / V^T as [48][68]
    __shared__ __align__(16) float sP[QT][MC];
    __shared__ float sM[QT], sSum[QT], sAl[QT];

    const float* qbase = &q[(size_t)((b*NHH + h) * LL) * DKK];
    const float* kbase = &k[(size_t)((b*NHH + h) * LL) * DKK];
    const float* vbase = &v[(size_t)((b*NHH + h) * LL) * DKK];
    const float* biasrow = &rel_bias[(size_t)h * NBIAS_];

    for (int e = tid; e < QT*48; e += 256)
        sq[e / 48][e % 48] = qbase[(size_t)(q0 + e/48) * 48 + (e % 48)];
    if (tid < QT) { sM[tid] = -1e30f; sSum[tid] = 0.f; }

    const int m4 = tx * 4;      // score cols
    const int d3 = tx * 3;      // PV cols
    float oacc[4][3];
    #pragma unroll
    for (int i = 0; i < 4; i++)
        #pragma unroll
        for (int c = 0; c < 3; c++) oacc[i][c] = 0.f;

    __syncthreads();

    for (int m0 = 0; m0 < LL; m0 += MC) {
        // ---- stage K chunk ----
        for (int e = tid; e < MC*48; e += 256) {
            int r = e / 48, c = e % 48;
            SK(r, c) = kbase[(size_t)(m0 + r) * 48 + c];
        }
        __syncthreads();

        // ---- scores: rows ty, ty+16, ty+32, ty+48 x cols m4..m4+3 ----
        {
            float s[4][4];
            #pragma unroll
            for (int i = 0; i < 4; i++)
                #pragma unroll
                for (int j = 0; j < 4; j++) s[i][j] = 0.f;

            #pragma unroll
            for (int d4 = 0; d4 < 48; d4 += 4) {
                float4 qa[4];
                #pragma unroll
                for (int i = 0; i < 4; i++)
                    qa[i] = *(const float4*)&sq[ty + 16*i][d4];
                #pragma unroll
                for (int j = 0; j < 4; j++) {
                    float4 kv = *(const float4*)&SK(m4 + j, d4);
                    #pragma unroll
                    for (int i = 0; i < 4; i++)
                        s[i][j] += qa[i].x*kv.x + qa[i].y*kv.y
                                 + qa[i].z*kv.z + qa[i].w*kv.w;
                }
            }
            #pragma unroll
            for (int i = 0; i < 4; i++) {
                int l = q0 + ty + 16*i;
                int ly = l >> 5, lx = l & 31;
                float4 outv;
                float* o = (float*)&outv;
                #pragma unroll
                for (int j = 0; j < 4; j++) {
                    int m = m0 + m4 + j;
                    int idx = ((m >> 5) - ly + 32) * 32 + ((m & 31) - lx + 32);
                    o[j] = s[i][j] + biasrow[idx];
                }
                *(float4*)&sP[ty + 16*i][m4] = outv;
            }
        }
        __syncthreads();

        // ---- online softmax (4 threads per row) + stage V^T ----
        {
            int r = tid >> 2, u = tid & 3;
            float cmax = -1e30f;
            #pragma unroll
            for (int mm = 0; mm < MC; mm += 4)
                cmax = fmaxf(cmax, sP[r][mm + u]);
            cmax = fmaxf(cmax, __shfl_xor_sync(0xffffffffu, cmax, 1));
            cmax = fmaxf(cmax, __shfl_xor_sync(0xffffffffu, cmax, 2));
            float newM = fmaxf(sM[r], cmax);
            float ssum = 0.f;
            #pragma unroll
            for (int mm = 0; mm < MC; mm += 4) {
                float p = expf(sP[r][mm + u] - newM);
                sP[r][mm + u] = p;
                ssum += p;
            }
            ssum += __shfl_xor_sync(0xffffffffu, ssum, 1);
            ssum += __shfl_xor_sync(0xffffffffu, ssum, 2);
            if (u == 0) {
                float al = expf(sM[r] - newM);
                sSum[r] = sSum[r] * al + ssum;
                sM[r]   = newM;
                sAl[r]  = al;
            }
        }
        // stage V transposed (safe: score phase done with sKV)
        for (int e = tid; e < MC*48; e += 256) {
            int r = e / 48, c = e % 48;
            SVT(c, r) = vbase[(size_t)(m0 + r) * 48 + c];
        }
        __syncthreads();

        // ---- PV: rows ty+16i x cols d3..d3+2 ----
        {
            float al[4];
            #pragma unroll
            for (int i = 0; i < 4; i++) {
                al[i] = sAl[ty + 16*i];
                #pragma unroll
                for (int c = 0; c < 3; c++) oacc[i][c] *= al[i];
            }
            #pragma unroll 4
            for (int mm = 0; mm < MC; mm += 4) {
                float4 p[4];
                #pragma unroll
                for (int i = 0; i < 4; i++)
                    p[i] = *(const float4*)&sP[ty + 16*i][mm];
                #pragma unroll
                for (int c = 0; c < 3; c++) {
                    float4 vv = *(const float4*)&SVT(d3 + c, mm);
                    #pragma unroll
                    for (int i = 0; i < 4; i++)
                        oacc[i][c] += p[i].x*vv.x + p[i].y*vv.y
                                    + p[i].z*vv.z + p[i].w*vv.w;
                }
            }
        }
        __syncthreads();
    }

    // ---- normalize + write [b, l, h*48+d] ----
    #pragma unroll
    for (int i = 0; i < 4; i++) {
        int r = ty + 16*i;
        float invs = 1.0f / sSum[r];
        #pragma unroll
        for (int c = 0; c < 3; c++)
            attn_out[(size_t)(b*LL + q0 + r) * (NHH*DVV) + h*DVV + d3 + c] =
                oacc[i][c] * invs;
    }
}

// ============================================================
// launch
// ============================================================
extern "C" void kernel_launch(void* const* d_in, const int* in_sizes, int n_in,
                              void* d_out, int out_size)
{
    (void)in_sizes; (void)n_in; (void)out_size;
    const float* x        = (const float*)d_in[0];
    const float* gamma    = (const float*)d_in[1];
    const float* beta     = (const float*)d_in[2];
    const float* Wq       = (const float*)d_in[3];
    const float* Wk       = (const float*)d_in[4];
    const float* Wv       = (const float*)d_in[5];
    const float* Wo       = (const float*)d_in[6];
    const float* bo       = (const float*)d_in[7];
    const float* rel_bias = (const float*)d_in[8];
    const float* fc1_w    = (const float*)d_in[9];
    const float* fc1_b    = (const float*)d_in[10];
    const float* fc2_w    = (const float*)d_in[11];
    const float* fc2_b    = (const float*)d_in[12];
    float* out = (float*)d_out;

    float *tok, *q, *k, *v, *attn, *ytok, *u1;
    cudaGetSymbolAddress((void**)&tok,  g_tok);
    cudaGetSymbolAddress((void**)&q,    g_q);
    cudaGetSymbolAddress((void**)&k,    g_k);
    cudaGetSymbolAddress((void**)&v,    g_v);
    cudaGetSymbolAddress((void**)&attn, g_attn);
    cudaGetSymbolAddress((void**)&ytok, g_ytok);
    cudaGetSymbolAddress((void**)&u1,   g_u1);

    const int M = BB * LL;   // 8192

    ln_kernel<<<dim3(LL/32, BB), dim3(32, 8)>>>(x, gamma, beta, tok);

    gemm128<2><<<dim3(384/64,  M/128), 256>>>(tok, Wq, nullptr, q, M, 384, 384, nullptr);
    gemm128<2><<<dim3(384/64,  M/128), 256>>>(tok, Wk, nullptr, k, M, 384, 384, nullptr);
    gemm128<2><<<dim3(384/64,  M/128), 256>>>(tok, Wv, nullptr, v, M, 384, 384, nullptr);

    attn_kernel<<<dim3(LL/QT, BB*NHH), 256>>>(q, k, v, rel_bias, attn);

    gemm128<3><<<dim3(384/64,  M/128), 256>>>(attn, Wo, bo, ytok, M, 384, 384, x);
    gemm128<1><<<dim3(1536/64, M/128), 256>>>(ytok, fc1_w, fc1_b, u1, M, 1536, 384, nullptr);
    gemm128<4><<<dim3(384/64,  M/128), 256>>>(u1, fc2_w, fc2_b, out, M, 384, 1536, ytok);
}

// round 3
// speedup vs baseline: 1.9269x; 1.2435x over previous
#include <cuda_runtime.h>
#include <math.h>

// ---- problem constants ----
#define BB   8
#define CC   384
#define LL   1024
#define NHH  8
#define DKK  48
#define DVV  48
#define CFF_ 1536
#define NBIAS_ 3969
#define LN_EPS_ 1e-5f

// ---- scratch ----
__device__ float g_tok [BB*LL*CC];
__device__ float g_q   [BB*NHH*LL*DKK];
__device__ float g_k   [BB*NHH*LL*DKK];
__device__ float g_v   [BB*NHH*LL*DKK];
__device__ float g_attn[BB*LL*NHH*DVV];
__device__ float g_ytok[BB*LL*CC];
__device__ float g_u1  [BB*LL*CFF_];

// ============================================================
// LayerNorm (unchanged from round 2)
// ============================================================
__global__ void ln_kernel(const float* __restrict__ x,
                          const float* __restrict__ gamma,
                          const float* __restrict__ beta,
                          float* __restrict__ tok)
{
    int b  = blockIdx.y;
    int l0 = blockIdx.x * 32;
    int lane = threadIdx.x;
    int cy   = threadIdx.y;

    __shared__ float redS [8][32];
    __shared__ float redS2[8][32];
    __shared__ float s_mu[32], s_inv[32];
    __shared__ float buf[64][33];

    float s = 0.f, s2 = 0.f;
    for (int c = cy; c < CC; c += 8) {
        float v = x[((size_t)b*CC + c)*LL + l0 + lane];
        s += v; s2 += v*v;
    }
    redS[cy][lane] = s; redS2[cy][lane] = s2;
    __syncthreads();
    if (cy == 0) {
        float ts = 0.f, ts2 = 0.f;
        #pragma unroll
        for (int i = 0; i < 8; i++) { ts += redS[i][lane]; ts2 += redS2[i][lane]; }
        float mu = ts * (1.0f/384.0f);
        float var = ts2 * (1.0f/384.0f) - mu*mu;
        s_mu[lane] = mu;
        s_inv[lane] = rsqrtf(var + LN_EPS_);
    }
    __syncthreads();

    int tid = cy*32 + lane;
    for (int c0 = 0; c0 < CC; c0 += 64) {
        for (int e = tid; e < 64*32; e += 256) {
            int c = e >> 5, t = e & 31;
            buf[c][t] = x[((size_t)b*CC + c0 + c)*LL + l0 + t];
        }
        __syncthreads();
        for (int e = tid; e < 64*32; e += 256) {
            int c = e & 63, t = e >> 6;
            float v = (buf[c][t] - s_mu[t]) * s_inv[t];
            tok[((size_t)b*LL + l0 + t)*CC + c0 + c] =
                v * gamma[c0 + c] + beta[c0 + c];
        }
        __syncthreads();
    }
}

// ============================================================
// GEMM (unchanged from round 2 — measured at fp32 SIMT issue ceiling)
// ============================================================
template<int MODE>
__global__ __launch_bounds__(256)
void gemm128(const float* __restrict__ A,
             const float* __restrict__ W,
             const float* __restrict__ bias,
             float* __restrict__ Out,
             int M, int N, int K,
             const float* __restrict__ aux)
{
    __shared__ __align__(16) float As[16][132];
    __shared__ __align__(16) float Bs[16][68];

    const int tid = threadIdx.x;
    const int m0 = blockIdx.y * 128;
    const int n0 = blockIdx.x * 64;
    const int tx = tid & 15;
    const int ty = tid >> 4;

    const int ra = tid >> 1, ka = (tid & 1) * 8;
    const int nb = tid >> 2, kb = (tid & 3) * 4;

    const float* Ap = A + (size_t)(m0 + ra) * K + ka;
    const float* Wp = W + (size_t)(n0 + nb) * K + kb;

    float4 a0 = *(const float4*)Ap;
    float4 a1 = *(const float4*)(Ap + 4);
    float4 b0 = *(const float4*)Wp;

    float acc[8][4];
    #pragma unroll
    for (int i = 0; i < 8; i++)
        #pragma unroll
        for (int j = 0; j < 4; j++) acc[i][j] = 0.f;

    for (int k0 = 0; k0 < K; k0 += 16) {
        As[ka+0][ra] = a0.x; As[ka+1][ra] = a0.y;
        As[ka+2][ra] = a0.z; As[ka+3][ra] = a0.w;
        As[ka+4][ra] = a1.x; As[ka+5][ra] = a1.y;
        As[ka+6][ra] = a1.z; As[ka+7][ra] = a1.w;
        Bs[kb+0][nb] = b0.x; Bs[kb+1][nb] = b0.y;
        Bs[kb+2][nb] = b0.z; Bs[kb+3][nb] = b0.w;
        __syncthreads();

        if (k0 + 16 < K) {
            Ap += 16; Wp += 16;
            a0 = *(const float4*)Ap;
            a1 = *(const float4*)(Ap + 4);
            b0 = *(const float4*)Wp;
        }

        #pragma unroll
        for (int kk = 0; kk < 16; kk++) {
            float4 av0 = *(const float4*)&As[kk][ty*8];
            float4 av1 = *(const float4*)&As[kk][ty*8 + 4];
            float4 bv  = *(const float4*)&Bs[kk][tx*4];
            float av[8] = {av0.x, av0.y, av0.z, av0.w, av1.x, av1.y, av1.z, av1.w};
            float bb[4] = {bv.x, bv.y, bv.z, bv.w};
            #pragma unroll
            for (int i = 0; i < 8; i++)
                #pragma unroll
                for (int j = 0; j < 4; j++)
                    acc[i][j] += av[i] * bb[j];
        }
        __syncthreads();
    }

    #pragma unroll
    for (int i = 0; i < 8; i++) {
        int row = m0 + ty*8 + i;
        int b = row >> 10, l = row & 1023;
        #pragma unroll
        for (int j = 0; j < 4; j++) {
            int col = n0 + tx*4 + j;
            float v = acc[i][j] + (bias ? bias[col] : 0.f);
            if (MODE == 1) {
                Out[(size_t)row * N + col] =
                    0.5f * v * (1.0f + erff(v * 0.70710678118654752f));
            } else if (MODE == 2) {
                int h = col / 48, d = col % 48;
                Out[(size_t)(((b*8 + h) * 1024) + l) * 48 + d] = v;
            } else if (MODE == 3) {
                Out[(size_t)row * 384 + col] =
                    v + aux[(size_t)(b*384 + col) * 1024 + l];
            } else { // MODE 4
                Out[(size_t)(b*384 + col) * 1024 + l] =
                    v + aux[(size_t)row * 384 + col];
            }
        }
    }
}

// ============================================================
// Flash attention v2: register softmax via shfl row-reduction.
// grid (L/64, B*NH), block 256 (tx 0..15 = row lanes, ty 0..15).
// Row group = fixed ty = 16-lane half-warp -> shfl_xor 1/2/4/8.
// K (padded to 52) and V^T (stride 68) share one phased smem buffer.
// ============================================================
#define QT 64
#define MC 64

__global__ __launch_bounds__(256)
void attn_kernel(const float* __restrict__ q,
                 const float* __restrict__ k,
                 const float* __restrict__ v,
                 const float* __restrict__ rel_bias,
                 float* __restrict__ attn_out)
{
    int b  = blockIdx.y >> 3;
    int h  = blockIdx.y & 7;
    int q0 = blockIdx.x * QT;
    int tid = threadIdx.x;
    int tx = tid & 15;
    int ty = tid >> 4;

    __shared__ __align__(16) float sq[QT][48];
    __shared__ __align__(16) float sKV[64*52];      // K[64][52] / V^T[48][68]
    __shared__ __align__(16) float sP[QT][MC];
    __shared__ float sM[QT], sSum[QT];

    #define SK(m,d)  sKV[(m)*52 + (d)]
    #define SVT(d,m) sKV[(d)*68 + (m)]

    const float* qbase = &q[(size_t)((b*NHH + h) * LL) * DKK];
    const float* kbase = &k[(size_t)((b*NHH + h) * LL) * DKK];
    const float* vbase = &v[(size_t)((b*NHH + h) * LL) * DKK];
    const float* biasrow = &rel_bias[(size_t)h * NBIAS_];

    for (int e = tid; e < QT*48; e += 256)
        sq[e / 48][e % 48] = qbase[(size_t)(q0 + e/48) * 48 + (e % 48)];
    if (tid < QT) { sM[tid] = -1e30f; sSum[tid] = 0.f; }
    __syncthreads();

    const int m4 = tx * 4;
    const int d3 = tx * 3;
    float oacc[4][3];
    #pragma unroll
    for (int i = 0; i < 4; i++)
        #pragma unroll
        for (int c = 0; c < 3; c++) oacc[i][c] = 0.f;

    for (int m0 = 0; m0 < LL; m0 += MC) {
        // ---- phase 1: stage K ----
        for (int e = tid; e < MC*48; e += 256) {
            int r = e / 48, c = e % 48;
            SK(r, c) = kbase[(size_t)(m0 + r) * 48 + c];
        }
        __syncthreads();

        // ---- phase 2: scores in regs + bias + register softmax ----
        float s[4][4];
        #pragma unroll
        for (int i = 0; i < 4; i++)
            #pragma unroll
            for (int j = 0; j < 4; j++) s[i][j] = 0.f;

        #pragma unroll
        for (int d4 = 0; d4 < 48; d4 += 4) {
            float4 qa[4];
            #pragma unroll
            for (int i = 0; i < 4; i++)
                qa[i] = *(const float4*)&sq[ty + 16*i][d4];
            #pragma unroll
            for (int j = 0; j < 4; j++) {
                float4 kv = *(const float4*)&SK(m4 + j, d4);
                #pragma unroll
                for (int i = 0; i < 4; i++)
                    s[i][j] += qa[i].x*kv.x + qa[i].y*kv.y
                             + qa[i].z*kv.z + qa[i].w*kv.w;
            }
        }

        float al[4];
        #pragma unroll
        for (int i = 0; i < 4; i++) {
            int r = ty + 16*i;
            int l = q0 + r;
            int ly = l >> 5, lx = l & 31;
            float mo = sM[r];
            float so = sSum[r];

            float rmax = -1e30f;
            #pragma unroll
            for (int j = 0; j < 4; j++) {
                int m = m0 + m4 + j;
                int idx = ((m >> 5) - ly + 32) * 32 + ((m & 31) - lx + 32);
                s[i][j] += biasrow[idx];
                rmax = fmaxf(rmax, s[i][j]);
            }
            #pragma unroll
            for (int o = 8; o > 0; o >>= 1)
                rmax = fmaxf(rmax, __shfl_xor_sync(0xffffffffu, rmax, o));

            float nm = fmaxf(mo, rmax);
            float rs = 0.f;
            #pragma unroll
            for (int j = 0; j < 4; j++) {
                float p = __expf(s[i][j] - nm);
                s[i][j] = p;
                rs += p;
            }
            #pragma unroll
            for (int o = 8; o > 0; o >>= 1)
                rs += __shfl_xor_sync(0xffffffffu, rs, o);

            al[i] = __expf(mo - nm);
            if (tx == 0) {
                sM[r]   = nm;
                sSum[r] = so * al[i] + rs;
            }
            float4 pv = make_float4(s[i][0], s[i][1], s[i][2], s[i][3]);
            *(float4*)&sP[r][m4] = pv;
        }
        __syncthreads();

        // ---- phase 3: stage V^T (reuses K buffer) ----
        for (int e = tid; e < MC*48; e += 256) {
            int r = e / 48, c = e % 48;
            SVT(c, r) = vbase[(size_t)(m0 + r) * 48 + c];
        }
        __syncthreads();

        // ---- phase 4: PV ----
        #pragma unroll
        for (int i = 0; i < 4; i++)
            #pragma unroll
            for (int c = 0; c < 3; c++) oacc[i][c] *= al[i];

        #pragma unroll 4
        for (int mm = 0; mm < MC; mm += 4) {
            float4 p[4];
            #pragma unroll
            for (int i = 0; i < 4; i++)
                p[i] = *(const float4*)&sP[ty + 16*i][mm];
            #pragma unroll
            for (int c = 0; c < 3; c++) {
                float4 vv = *(const float4*)&SVT(d3 + c, mm);
                #pragma unroll
                for (int i = 0; i < 4; i++)
                    oacc[i][c] += p[i].x*vv.x + p[i].y*vv.y
                                + p[i].z*vv.z + p[i].w*vv.w;
            }
        }
        __syncthreads();
    }

    #pragma unroll
    for (int i = 0; i < 4; i++) {
        int r = ty + 16*i;
        float invs = 1.0f / sSum[r];
        #pragma unroll
        for (int c = 0; c < 3; c++)
            attn_out[(size_t)(b*LL + q0 + r) * (NHH*DVV) + h*DVV + d3 + c] =
                oacc[i][c] * invs;
    }
}

// ============================================================
// launch
// ============================================================
extern "C" void kernel_launch(void* const* d_in, const int* in_sizes, int n_in,
                              void* d_out, int out_size)
{
    (void)in_sizes; (void)n_in; (void)out_size;
    const float* x        = (const float*)d_in[0];
    const float* gamma    = (const float*)d_in[1];
    const float* beta     = (const float*)d_in[2];
    const float* Wq       = (const float*)d_in[3];
    const float* Wk       = (const float*)d_in[4];
    const float* Wv       = (const float*)d_in[5];
    const float* Wo       = (const float*)d_in[6];
    const float* bo       = (const float*)d_in[7];
    const float* rel_bias = (const float*)d_in[8];
    const float* fc1_w    = (const float*)d_in[9];
    const float* fc1_b    = (const float*)d_in[10];
    const float* fc2_w    = (const float*)d_in[11];
    const float* fc2_b    = (const float*)d_in[12];
    float* out = (float*)d_out;

    float *tok, *q, *k, *v, *attn, *ytok, *u1;
    cudaGetSymbolAddress((void**)&tok,  g_tok);
    cudaGetSymbolAddress((void**)&q,    g_q);
    cudaGetSymbolAddress((void**)&k,    g_k);
    cudaGetSymbolAddress((void**)&v,    g_v);
    cudaGetSymbolAddress((void**)&attn, g_attn);
    cudaGetSymbolAddress((void**)&ytok, g_ytok);
    cudaGetSymbolAddress((void**)&u1,   g_u1);

    const int M = BB * LL;

    ln_kernel<<<dim3(LL/32, BB), dim3(32, 8)>>>(x, gamma, beta, tok);

    gemm128<2><<<dim3(384/64,  M/128), 256>>>(tok, Wq, nullptr, q, M, 384, 384, nullptr);
    gemm128<2><<<dim3(384/64,  M/128), 256>>>(tok, Wk, nullptr, k, M, 384, 384, nullptr);
    gemm128<2><<<dim3(384/64,  M/128), 256>>>(tok, Wv, nullptr, v, M, 384, 384, nullptr);

    attn_kernel<<<dim3(LL/QT, BB*NHH), 256>>>(q, k, v, rel_bias, attn);

    gemm128<3><<<dim3(384/64,  M/128), 256>>>(attn, Wo, bo, ytok, M, 384, 384, x);
    gemm128<1><<<dim3(1536/64, M/128), 256>>>(ytok, fc1_w, fc1_b, u1, M, 1536, 384, nullptr);
    gemm128<4><<<dim3(384/64,  M/128), 256>>>(u1, fc2_w, fc2_b, out, M, 384, 1536, ytok);
}